// round 1
// baseline (speedup 1.0000x reference)
#include <cuda_runtime.h>
#include <cuda_bf16.h>

// Problem constants (AtomicNeuralNetwork): N=4096, A=256, D_IN=39, H=50, S=8
#define D_IN  39
#define H_    50
#define A_    256
#define NP    26          // padded pair count (52 floats per weight row)
#define ROW_F (NP * 2)    // 52 floats per padded row (208 B, 16B-aligned rows)
#define TPB   128

// ---- packed f32x2 helpers (sm_100a) ----
__device__ __forceinline__ unsigned long long pack2(float lo, float hi) {
    unsigned long long r;
    asm("mov.b64 %0, {%1, %2};" : "=l"(r) : "f"(lo), "f"(hi));
    return r;
}
__device__ __forceinline__ void fma2(unsigned long long& d,
                                     unsigned long long a,
                                     unsigned long long b) {
    asm("fma.rn.f32x2 %0, %1, %2, %0;" : "+l"(d) : "l"(a), "l"(b));
}
__device__ __forceinline__ void unpack2(unsigned long long v, float& lo, float& hi) {
    asm("mov.b64 {%0, %1}, %2;" : "=f"(lo), "=f"(hi) : "l"(v));
}
__device__ __forceinline__ float silu_f(float x) {
    // x * sigmoid(x); __expf rel-err ~1e-6, far inside the 1e-3 gate
    return x * (1.0f / (1.0f + __expf(-x)));
}

__global__ void __launch_bounds__(TPB, 3) atomic_mlp_kernel(
    const float* __restrict__ desc,     // [N, A, D_IN]
    const int*   __restrict__ numbers,  // [A]
    const float* __restrict__ W1,       // [S, D_IN, H]
    const float* __restrict__ b1,       // [S, H]
    const float* __restrict__ W2,       // [S, H, H]
    const float* __restrict__ b2,       // [S, H]
    const float* __restrict__ W3,       // [S, H, 1]
    const float* __restrict__ b3,       // [S, 1]
    float* __restrict__ out)            // [N, A]
{
    __shared__ __align__(16) float sW1[D_IN * ROW_F];  // 8.1 KB
    __shared__ __align__(16) float sW2[H_   * ROW_F];  // 10.4 KB
    __shared__ __align__(16) float sB1[ROW_F];
    __shared__ __align__(16) float sB2[ROW_F];
    __shared__ float sW3[H_];
    __shared__ float sB3;
    __shared__ float sX[TPB * D_IN];                   // 19.5 KB desc tile

    const int a   = blockIdx.x;
    const int tid = threadIdx.x;
    const int s   = numbers[a];

    // ---- stage species weights (zero-padded rows for clean LDS.128) ----
    {
        const float* w1 = W1 + s * (D_IN * H_);
        for (int i = tid; i < D_IN * ROW_F; i += TPB) {
            int d = i / ROW_F, h = i - d * ROW_F;
            sW1[i] = (h < H_) ? w1[d * H_ + h] : 0.0f;
        }
        const float* w2 = W2 + s * (H_ * H_);
        for (int i = tid; i < H_ * ROW_F; i += TPB) {
            int k = i / ROW_F, h = i - k * ROW_F;
            sW2[i] = (h < H_) ? w2[k * H_ + h] : 0.0f;
        }
        if (tid < ROW_F) {
            sB1[tid] = (tid < H_) ? b1[s * H_ + tid] : 0.0f;
            sB2[tid] = (tid < H_) ? b2[s * H_ + tid] : 0.0f;
        }
        if (tid < H_) sW3[tid] = W3[s * H_ + tid];
        if (tid == 0) sB3 = b3[s];
    }

    // ---- stage desc tile, coalesced (each warp reads contiguous runs) ----
    const int n0 = blockIdx.y * TPB;
    {
        const float* dbase = desc + ((size_t)n0 * A_ + a) * D_IN;
        for (int i = tid; i < TPB * D_IN; i += TPB) {
            int nl = i / D_IN, d = i - nl * D_IN;
            sX[i] = dbase[(size_t)nl * (A_ * D_IN) + d];
        }
    }
    __syncthreads();

    // per-thread input row (stride 39 is odd -> bank-conflict-free)
    float x[D_IN];
#pragma unroll
    for (int d = 0; d < D_IN; d++) x[d] = sX[tid * D_IN + d];

    unsigned long long acc[NP];

    // ================= Layer 1: [39] -> [50], silu =================
    {
        const ulonglong2* bv = (const ulonglong2*)sB1;
#pragma unroll
        for (int q = 0; q < NP / 2; q++) {
            ulonglong2 t = bv[q];
            acc[2 * q] = t.x; acc[2 * q + 1] = t.y;
        }
#pragma unroll
        for (int d = 0; d < D_IN; d++) {
            unsigned long long xd = pack2(x[d], x[d]);
            const ulonglong2* row = (const ulonglong2*)(sW1 + d * ROW_F);
#pragma unroll
            for (int q = 0; q < NP / 2; q++) {
                ulonglong2 w = row[q];          // LDS.128, broadcast
                fma2(acc[2 * q],     xd, w.x);
                fma2(acc[2 * q + 1], xd, w.y);
            }
        }
    }
    float h1[H_];
#pragma unroll
    for (int p = 0; p < H_ / 2; p++) {
        float lo, hi; unpack2(acc[p], lo, hi);
        h1[2 * p]     = silu_f(lo);
        h1[2 * p + 1] = silu_f(hi);
    }

    // ================= Layer 2: [50] -> [50], silu =================
    {
        const ulonglong2* bv = (const ulonglong2*)sB2;
#pragma unroll
        for (int q = 0; q < NP / 2; q++) {
            ulonglong2 t = bv[q];
            acc[2 * q] = t.x; acc[2 * q + 1] = t.y;
        }
#pragma unroll
        for (int h = 0; h < H_; h++) {
            unsigned long long xh = pack2(h1[h], h1[h]);
            const ulonglong2* row = (const ulonglong2*)(sW2 + h * ROW_F);
#pragma unroll
            for (int q = 0; q < NP / 2; q++) {
                ulonglong2 w = row[q];
                fma2(acc[2 * q],     xh, w.x);
                fma2(acc[2 * q + 1], xh, w.y);
            }
        }
    }

    // ================= Layer 3: [50] -> 1 =================
    float o = sB3;
#pragma unroll
    for (int p = 0; p < H_ / 2; p++) {
        float lo, hi; unpack2(acc[p], lo, hi);
        o += silu_f(lo) * sW3[2 * p] + silu_f(hi) * sW3[2 * p + 1];
    }

    const int n = n0 + tid;
    out[(size_t)n * A_ + a] = o;
}

extern "C" void kernel_launch(void* const* d_in, const int* in_sizes, int n_in,
                              void* d_out, int out_size) {
    const float* desc    = (const float*)d_in[0];
    const int*   numbers = (const int*)  d_in[1];
    const float* W1      = (const float*)d_in[2];
    const float* b1      = (const float*)d_in[3];
    const float* W2      = (const float*)d_in[4];
    const float* b2      = (const float*)d_in[5];
    const float* W3      = (const float*)d_in[6];
    const float* b3      = (const float*)d_in[7];
    float* out = (float*)d_out;

    const int N = in_sizes[0] / (A_ * D_IN);   // 4096
    dim3 grid(A_, (unsigned)(N / TPB));        // (256, 32)
    atomic_mlp_kernel<<<grid, TPB>>>(desc, numbers, W1, b1, W2, b2, W3, b3, out);
}

// round 4
// speedup vs baseline: 2.1335x; 2.1335x over previous
#include <cuda_runtime.h>
#include <cuda_bf16.h>
#include <cstdint>

// AtomicNeuralNetwork: N=4096, A=256, D_IN=39, H=50, S=8
#define D_IN 39
#define H_   50
#define A_   256
#define S_   8
#define TPB  256

// ---- smem layout (bytes). Strides 112/144 are odd multiples of 16 mod 128
// -> 8 consecutive rows hit 8 distinct 16B columns -> ldmatrix conflict-free.
#define STR1 112           // layer-1 panels: kpad=48 (96B data)
#define STR2 144           // layer-2 panels: kpad=64 (128B data)
#define A1H  0             // 128*112 = 14336
#define A1L  14336
#define A2H  28672         // 128*144 = 18432
#define A2L  47104
#define B1H  65536         // 64*112 = 7168
#define B1L  72704
#define B2H  79872         // 64*144 = 9216
#define B2L  89088
#define SB1  98304         // 64 floats
#define SB2  98560
#define SW3  98816
#define SPART 99072        // 2*128 floats
#define SB3  100096
#define SMEM_BYTES 100352

// packed per-species weights: [B1H | B1L | B2H | B2L] in u16 units
#define W_B1H 0
#define W_B1L 3584
#define W_B2H 7168
#define W_B2L 11776
#define W_TOT 16384        // u16 elements = 32768 bytes

__device__ __align__(16) uint16_t g_W[S_][W_TOT];

// ---------------- helpers ----------------
__device__ __forceinline__ uint32_t smem_u32(const void* p) {
    uint32_t a;
    asm("{ .reg .u64 t; cvta.to.shared.u64 t, %1; cvt.u32.u64 %0, t; }" : "=r"(a) : "l"(p));
    return a;
}
__device__ __forceinline__ void ldsm4(uint32_t* r, uint32_t addr) {
    asm volatile("ldmatrix.sync.aligned.m8n8.x4.shared.b16 {%0,%1,%2,%3}, [%4];"
        : "=r"(r[0]), "=r"(r[1]), "=r"(r[2]), "=r"(r[3]) : "r"(addr));
}
__device__ __forceinline__ void mma16816(float* c, const uint32_t* a, const uint32_t* b) {
    asm volatile("mma.sync.aligned.m16n8k16.row.col.f32.bf16.bf16.f32 "
        "{%0,%1,%2,%3}, {%4,%5,%6,%7}, {%8,%9}, {%0,%1,%2,%3};"
        : "+f"(c[0]), "+f"(c[1]), "+f"(c[2]), "+f"(c[3])
        : "r"(a[0]), "r"(a[1]), "r"(a[2]), "r"(a[3]), "r"(b[0]), "r"(b[1]));
}
#define STS32(addr, v) \
    asm volatile("st.shared.u32 [%0], %1;" :: "r"(addr), "r"(v) : "memory")
#define STS16(addr, v) \
    asm volatile("st.shared.u16 [%0], %1;" :: "r"(addr), "h"((uint16_t)(v)) : "memory")

__device__ __forceinline__ float silu_f(float x) {
    float e, r;
    asm("ex2.approx.f32 %0, %1;" : "=f"(e) : "f"(x * -1.44269504f));
    asm("rcp.approx.f32 %0, %1;" : "=f"(r) : "f"(1.0f + e));
    return x * r;
}

// ---------------- weight prep: split-bf16 B panels, [n][k] layout ----------------
// hi = rn_bf16(w), lo = rn_bf16(w - hi). Pads exactly zero.
__global__ void prep_kernel(const float* __restrict__ W1, const float* __restrict__ W2) {
    int s = blockIdx.x, tid = threadIdx.x;
    for (int idx = tid; idx < 3584 + 4608; idx += blockDim.x) {
        float w; int off_hi, off_lo;
        if (idx < 3584) {                       // layer 1: n 0-63, k 0-55
            int n = idx / 56, k = idx % 56;
            w = (n < H_ && k < D_IN) ? W1[s * D_IN * H_ + k * H_ + n] : 0.0f;
            off_hi = W_B1H + idx; off_lo = W_B1L + idx;
        } else {                                // layer 2: n 0-63, k 0-71
            int j = idx - 3584;
            int n = j / 72, k = j % 72;
            w = (n < H_ && k < H_) ? W2[s * H_ * H_ + k * H_ + n] : 0.0f;
            off_hi = W_B2H + j; off_lo = W_B2L + j;
        }
        __nv_bfloat16 hi = __float2bfloat16(w);
        __nv_bfloat16 lo = __float2bfloat16(w - __bfloat162float(hi));
        g_W[s][off_hi] = __bfloat16_as_ushort(hi);
        g_W[s][off_lo] = __bfloat16_as_ushort(lo);
    }
}

// ---------------- main kernel ----------------
__global__ void __launch_bounds__(TPB, 2) atomic_mlp_mma(
    const float* __restrict__ desc,     // [N, A, D_IN]
    const int*   __restrict__ numbers,  // [A]
    const float* __restrict__ b1, const float* __restrict__ b2,
    const float* __restrict__ W3, const float* __restrict__ b3,
    float* __restrict__ out)            // [N, A]
{
    extern __shared__ __align__(128) unsigned char smem[];
    const uint32_t sb = smem_u32(smem);
    const int tid = threadIdx.x;
    const int wid = tid >> 5, lid = tid & 31;
    const int wg  = wid >> 2;            // 0/1: n-half
    const int mq  = wid & 3;             // m quarter
    const int mbase = mq * 32, nbase = wg * 32;
    const int g = lid >> 2, tig = lid & 3;
    const int a = blockIdx.x;
    const int s = numbers[a];

    float* sB1f = (float*)(smem + SB1);
    float* sB2f = (float*)(smem + SB2);
    float* sW3f = (float*)(smem + SW3);
    float* sPart = (float*)(smem + SPART);
    float* sB3f = (float*)(smem + SB3);

    // zero A panels (k-pads must stay zero forever)
    for (int i = tid; i < 65536 / 16; i += TPB)
        ((float4*)smem)[i] = make_float4(0.f, 0.f, 0.f, 0.f);
    // copy species weight panels (contiguous 32 KB)
    {
        const float4* src = (const float4*)g_W[s];
        float4* dst = (float4*)(smem + B1H);
        for (int i = tid; i < 32768 / 16; i += TPB) dst[i] = src[i];
    }
    if (tid < 64) {
        sB1f[tid] = (tid < H_) ? b1[s * H_ + tid] : 0.0f;
        sB2f[tid] = (tid < H_) ? b2[s * H_ + tid] : 0.0f;
        sW3f[tid] = (tid < H_) ? W3[s * H_ + tid] : 0.0f;
    }
    if (tid == 0) *sB3f = b3[s];

    // ldmatrix lane offsets (lane supplies one 8x8-row address)
    const int lm = lid >> 3, rin = lid & 7;
    const uint32_t aoff1 = (uint32_t)((mbase + rin + (lm & 1) * 8) * STR1 + (lm >> 1) * 16);
    const uint32_t aoff2 = (uint32_t)((mbase + rin + (lm & 1) * 8) * STR2 + (lm >> 1) * 16);
    const uint32_t boff1 = (uint32_t)((nbase + rin + (lm >> 1) * 8) * STR1 + (lm & 1) * 16);
    const uint32_t boff2 = (uint32_t)((nbase + rin + (lm >> 1) * 8) * STR2 + (lm & 1) * 16);

    const int njmax = (wg == 1) ? 3 : 4;   // n 56-63 is all-pad for wg1 epilogues

    const int chunk = blockIdx.y;
    for (int t = 0; t < 4; t++) {
        const int n0 = (chunk * 4 + t) * 128;

        // ---- stage desc tile -> A1 hi/lo panels ----
        {
            const float* dbase = desc + ((size_t)n0 * A_ + a) * D_IN;
            for (int idx = tid; idx < 128 * D_IN; idx += TPB) {
                int i = idx / D_IN, d = idx - i * D_IN;
                float x = dbase[(size_t)i * (A_ * D_IN) + d];
                uint32_t xb = __float_as_uint(x);
                uint32_t hb = xb & 0xFFFF0000u;                 // truncation split
                __nv_bfloat16 lo = __float2bfloat16(x - __uint_as_float(hb));
                uint32_t ad = sb + (uint32_t)(i * STR1 + d * 2);
                STS16(A1H + ad, (uint16_t)(xb >> 16));
                STS16(A1L + ad, __bfloat16_as_ushort(lo));
            }
        }
        __syncthreads();

        float acc[2][4][4];
#pragma unroll
        for (int mi = 0; mi < 2; mi++)
#pragma unroll
            for (int nj = 0; nj < 4; nj++)
#pragma unroll
                for (int r = 0; r < 4; r++) acc[mi][nj][r] = 0.0f;

        // ---- layer 1 MMAs: K = 48 (3 k16 steps), 3 split terms ----
#pragma unroll
        for (int ks = 0; ks < 3; ks++) {
            const uint32_t kb = ks * 32;
            uint32_t ah0[4], ah1[4], al0[4], al1[4], bh[8], bl[8];
            ldsm4(ah0, sb + A1H + aoff1 + kb);
            ldsm4(ah1, sb + A1H + aoff1 + 16 * STR1 + kb);
            ldsm4(al0, sb + A1L + aoff1 + kb);
            ldsm4(al1, sb + A1L + aoff1 + 16 * STR1 + kb);
            ldsm4(bh + 0, sb + B1H + boff1 + kb);
            ldsm4(bh + 4, sb + B1H + boff1 + 16 * STR1 + kb);
            ldsm4(bl + 0, sb + B1L + boff1 + kb);
            ldsm4(bl + 4, sb + B1L + boff1 + 16 * STR1 + kb);
#pragma unroll
            for (int nj = 0; nj < 4; nj++) {
                mma16816(acc[0][nj], ah0, bh + 2 * nj);
                mma16816(acc[0][nj], al0, bh + 2 * nj);
                mma16816(acc[0][nj], ah0, bl + 2 * nj);
                mma16816(acc[1][nj], ah1, bh + 2 * nj);
                mma16816(acc[1][nj], al1, bh + 2 * nj);
                mma16816(acc[1][nj], ah1, bl + 2 * nj);
            }
        }

        // ---- epilogue 1: +b1, silu, split, write A2 hi/lo panels ----
        {
            float2 b1v[4];
#pragma unroll
            for (int nj = 0; nj < 4; nj++)
                b1v[nj] = *(const float2*)&sB1f[nbase + 8 * nj + 2 * tig];
#pragma unroll
            for (int mi = 0; mi < 2; mi++)
#pragma unroll
                for (int nj = 0; nj < 4; nj++) {
                    if (nj >= njmax) break;
                    const float* c = acc[mi][nj];
                    float h0 = silu_f(c[0] + b1v[nj].x);
                    float h1 = silu_f(c[1] + b1v[nj].y);
                    float h2 = silu_f(c[2] + b1v[nj].x);
                    float h3 = silu_f(c[3] + b1v[nj].y);
                    uint32_t hb0 = __float_as_uint(h0) & 0xFFFF0000u;
                    uint32_t hb1 = __float_as_uint(h1) & 0xFFFF0000u;
                    uint32_t hb2 = __float_as_uint(h2) & 0xFFFF0000u;
                    uint32_t hb3 = __float_as_uint(h3) & 0xFFFF0000u;
                    uint32_t u01 = __byte_perm(hb0, hb1, 0x7632);
                    uint32_t u23 = __byte_perm(hb2, hb3, 0x7632);
                    uint32_t l01, l23;
                    asm("cvt.rn.bf16x2.f32 %0, %1, %2;" : "=r"(l01)
                        : "f"(h1 - __uint_as_float(hb1)), "f"(h0 - __uint_as_float(hb0)));
                    asm("cvt.rn.bf16x2.f32 %0, %1, %2;" : "=r"(l23)
                        : "f"(h3 - __uint_as_float(hb3)), "f"(h2 - __uint_as_float(hb2)));
                    uint32_t r0 = (uint32_t)(mbase + mi * 16 + g);
                    uint32_t c0 = (uint32_t)(nbase + nj * 8 + 2 * tig);
                    uint32_t ad = sb + r0 * STR2 + c0 * 2;
                    STS32(A2H + ad, u01);
                    STS32(A2H + ad + 8 * STR2, u23);
                    STS32(A2L + ad, l01);
                    STS32(A2L + ad + 8 * STR2, l23);
                }
        }
        __syncthreads();

#pragma unroll
        for (int mi = 0; mi < 2; mi++)
#pragma unroll
            for (int nj = 0; nj < 4; nj++)
#pragma unroll
                for (int r = 0; r < 4; r++) acc[mi][nj][r] = 0.0f;

        // ---- layer 2 MMAs: K = 64 (4 k16 steps), 3 split terms ----
#pragma unroll
        for (int ks = 0; ks < 4; ks++) {
            const uint32_t kb = ks * 32;
            uint32_t ah0[4], ah1[4], al0[4], al1[4], bh[8], bl[8];
            ldsm4(ah0, sb + A2H + aoff2 + kb);
            ldsm4(ah1, sb + A2H + aoff2 + 16 * STR2 + kb);
            ldsm4(al0, sb + A2L + aoff2 + kb);
            ldsm4(al1, sb + A2L + aoff2 + 16 * STR2 + kb);
            ldsm4(bh + 0, sb + B2H + boff2 + kb);
            ldsm4(bh + 4, sb + B2H + boff2 + 16 * STR2 + kb);
            ldsm4(bl + 0, sb + B2L + boff2 + kb);
            ldsm4(bl + 4, sb + B2L + boff2 + 16 * STR2 + kb);
#pragma unroll
            for (int nj = 0; nj < 4; nj++) {
                mma16816(acc[0][nj], ah0, bh + 2 * nj);
                mma16816(acc[0][nj], al0, bh + 2 * nj);
                mma16816(acc[0][nj], ah0, bl + 2 * nj);
                mma16816(acc[1][nj], ah1, bh + 2 * nj);
                mma16816(acc[1][nj], al1, bh + 2 * nj);
                mma16816(acc[1][nj], ah1, bl + 2 * nj);
            }
        }

        // ---- epilogue 2: +b2, silu, dot w3, reduce, write out ----
        {
            float2 b2v[4], w3v[4];
#pragma unroll
            for (int nj = 0; nj < 4; nj++) {
                b2v[nj] = *(const float2*)&sB2f[nbase + 8 * nj + 2 * tig];
                w3v[nj] = *(const float2*)&sW3f[nbase + 8 * nj + 2 * tig];
            }
            float p[4] = {0.f, 0.f, 0.f, 0.f};   // rows: mi*16 + {g, g+8}
#pragma unroll
            for (int mi = 0; mi < 2; mi++)
#pragma unroll
                for (int nj = 0; nj < 4; nj++) {
                    if (nj >= njmax) break;
                    const float* c = acc[mi][nj];
                    p[2 * mi]     += silu_f(c[0] + b2v[nj].x) * w3v[nj].x
                                   + silu_f(c[1] + b2v[nj].y) * w3v[nj].y;
                    p[2 * mi + 1] += silu_f(c[2] + b2v[nj].x) * w3v[nj].x
                                   + silu_f(c[3] + b2v[nj].y) * w3v[nj].y;
                }
#pragma unroll
            for (int i = 0; i < 4; i++) {
                p[i] += __shfl_xor_sync(0xFFFFFFFFu, p[i], 1);
                p[i] += __shfl_xor_sync(0xFFFFFFFFu, p[i], 2);
            }
            if (tig == 0) {
                sPart[wg * 128 + mbase + g]      = p[0];
                sPart[wg * 128 + mbase + g + 8]  = p[1];
                sPart[wg * 128 + mbase + 16 + g]     = p[2];
                sPart[wg * 128 + mbase + 16 + g + 8] = p[3];
            }
            __syncthreads();
            if (tid < 128) {
                float o = sPart[tid] + sPart[128 + tid] + *sB3f;
                out[(size_t)(n0 + tid) * A_ + a] = o;
            }
        }
        __syncthreads();
    }
}

extern "C" void kernel_launch(void* const* d_in, const int* in_sizes, int n_in,
                              void* d_out, int out_size) {
    const float* desc    = (const float*)d_in[0];
    const int*   numbers = (const int*)  d_in[1];
    const float* W1      = (const float*)d_in[2];
    const float* b1      = (const float*)d_in[3];
    const float* W2      = (const float*)d_in[4];
    const float* b2      = (const float*)d_in[5];
    const float* W3      = (const float*)d_in[6];
    const float* b3      = (const float*)d_in[7];
    float* out = (float*)d_out;

    const int N = in_sizes[0] / (A_ * D_IN);   // 4096
    prep_kernel<<<S_, 256>>>(W1, W2);
    cudaFuncSetAttribute(atomic_mlp_mma, cudaFuncAttributeMaxDynamicSharedMemorySize, SMEM_BYTES);
    dim3 grid(A_, (unsigned)(N / 512));        // (256, 8)
    atomic_mlp_mma<<<grid, TPB, SMEM_BYTES>>>(desc, numbers, b1, b2, W3, b3, out);
}

// round 5
// speedup vs baseline: 2.8017x; 1.3132x over previous
#include <cuda_runtime.h>
#include <cuda_bf16.h>
#include <cstdint>

// AtomicNeuralNetwork: N=4096, A=256, D_IN=39, H=50, S=8
#define D_IN 39
#define H_   50
#define A_   256
#define S_   8
#define TPB  512

// ---- smem layout (bytes). Strides 112/144 are odd multiples of 16 mod 128
// -> 8 consecutive rows hit 8 distinct 16B columns -> ldmatrix conflict-free.
#define STR1 112           // layer-1 panels: kpad=48 (96B data)
#define STR2 144           // layer-2 panels: kpad=64 (128B data)
#define A1H  0             // 128*112 = 14336
#define A1L  14336
#define A2H  28672         // 128*144 = 18432
#define A2L  47104
#define B1H  65536         // 64*112 = 7168
#define B1L  72704
#define B2H  79872         // 64*144 = 9216
#define B2L  89088
#define SB1  98304         // 64 floats
#define SB2  98560
#define SW3  98816
#define SPART 99072        // 2*128 floats
#define SB3  100096
#define SMEM_BYTES 100352

// packed per-species weights: [B1H | B1L | B2H | B2L] in u16 units
#define W_B1H 0
#define W_B1L 3584
#define W_B2H 7168
#define W_B2L 11776
#define W_TOT 16384        // u16 elements = 32768 bytes

__device__ __align__(16) uint16_t g_W[S_][W_TOT];

// ---------------- helpers ----------------
__device__ __forceinline__ uint32_t smem_u32(const void* p) {
    uint32_t a;
    asm("{ .reg .u64 t; cvta.to.shared.u64 t, %1; cvt.u32.u64 %0, t; }" : "=r"(a) : "l"(p));
    return a;
}
__device__ __forceinline__ void ldsm4(uint32_t* r, uint32_t addr) {
    asm volatile("ldmatrix.sync.aligned.m8n8.x4.shared.b16 {%0,%1,%2,%3}, [%4];"
        : "=r"(r[0]), "=r"(r[1]), "=r"(r[2]), "=r"(r[3]) : "r"(addr));
}
__device__ __forceinline__ void mma16816(float* c, const uint32_t* a, const uint32_t* b) {
    asm volatile("mma.sync.aligned.m16n8k16.row.col.f32.bf16.bf16.f32 "
        "{%0,%1,%2,%3}, {%4,%5,%6,%7}, {%8,%9}, {%0,%1,%2,%3};"
        : "+f"(c[0]), "+f"(c[1]), "+f"(c[2]), "+f"(c[3])
        : "r"(a[0]), "r"(a[1]), "r"(a[2]), "r"(a[3]), "r"(b[0]), "r"(b[1]));
}
#define STS32(addr, v) \
    asm volatile("st.shared.u32 [%0], %1;" :: "r"(addr), "r"(v) : "memory")
#define STS16(addr, v) \
    asm volatile("st.shared.u16 [%0], %1;" :: "r"(addr), "h"((uint16_t)(v)) : "memory")

// silu via single-MUFU tanh: silu(x) = s + s*tanh(s), s = x/2
__device__ __forceinline__ float silu_f(float x) {
    float s = 0.5f * x, t;
    asm("tanh.approx.f32 %0, %1;" : "=f"(t) : "f"(s));
    return fmaf(s, t, s);
}

// ---------------- weight prep: split-bf16 B panels, [n][k] layout ----------------
// hi = rn_bf16(w), lo = rn_bf16(w - hi). Pads exactly zero.
__global__ void prep_kernel(const float* __restrict__ W1, const float* __restrict__ W2) {
    int s = blockIdx.x, tid = threadIdx.x;
    for (int idx = tid; idx < 3584 + 4608; idx += blockDim.x) {
        float w; int off_hi, off_lo;
        if (idx < 3584) {                       // layer 1: n 0-63, k 0-55
            int n = idx / 56, k = idx % 56;
            w = (n < H_ && k < D_IN) ? W1[s * D_IN * H_ + k * H_ + n] : 0.0f;
            off_hi = W_B1H + idx; off_lo = W_B1L + idx;
        } else {                                // layer 2: n 0-63, k 0-71
            int j = idx - 3584;
            int n = j / 72, k = j % 72;
            w = (n < H_ && k < H_) ? W2[s * H_ * H_ + k * H_ + n] : 0.0f;
            off_hi = W_B2H + j; off_lo = W_B2L + j;
        }
        __nv_bfloat16 hi = __float2bfloat16(w);
        __nv_bfloat16 lo = __float2bfloat16(w - __bfloat162float(hi));
        g_W[s][off_hi] = __bfloat16_as_ushort(hi);
        g_W[s][off_lo] = __bfloat16_as_ushort(lo);
    }
}

// ---------------- main kernel ----------------
__global__ void __launch_bounds__(TPB, 2) atomic_mlp_mma(
    const float* __restrict__ desc,     // [N, A, D_IN]
    const int*   __restrict__ numbers,  // [A]
    const float* __restrict__ b1, const float* __restrict__ b2,
    const float* __restrict__ W3, const float* __restrict__ b3,
    float* __restrict__ out)            // [N, A]
{
    extern __shared__ __align__(128) unsigned char smem[];
    const uint32_t sb = smem_u32(smem);
    const int tid = threadIdx.x;
    const int wid = tid >> 5, lid = tid & 31;
    const int nhalf = wid >> 3;          // 0/1: n-half
    const int mq    = wid & 7;           // m sixteenth-block
    const int mbase = mq * 16, nbase = nhalf * 32;
    const int g = lid >> 2, tig = lid & 3;
    const int a = blockIdx.x;
    const int s = numbers[a];

    float* sB1f = (float*)(smem + SB1);
    float* sB2f = (float*)(smem + SB2);
    float* sW3f = (float*)(smem + SW3);
    float* sPart = (float*)(smem + SPART);
    float* sB3f = (float*)(smem + SB3);

    // zero A panels (k-pads must stay zero forever)
    for (int i = tid; i < 65536 / 16; i += TPB)
        ((float4*)smem)[i] = make_float4(0.f, 0.f, 0.f, 0.f);
    // copy species weight panels (contiguous 32 KB)
    {
        const float4* src = (const float4*)g_W[s];
        float4* dst = (float4*)(smem + B1H);
        for (int i = tid; i < 32768 / 16; i += TPB) dst[i] = src[i];
    }
    if (tid < 64) {
        sB1f[tid] = (tid < H_) ? b1[s * H_ + tid] : 0.0f;
        sB2f[tid] = (tid < H_) ? b2[s * H_ + tid] : 0.0f;
        sW3f[tid] = (tid < H_) ? W3[s * H_ + tid] : 0.0f;
    }
    if (tid == 0) *sB3f = b3[s];

    // ldmatrix lane offsets (lane supplies one 8x8-row address)
    const int lm = lid >> 3, rin = lid & 7;
    const uint32_t aoff1 = (uint32_t)((mbase + rin + (lm & 1) * 8) * STR1 + (lm >> 1) * 16);
    const uint32_t aoff2 = (uint32_t)((mbase + rin + (lm & 1) * 8) * STR2 + (lm >> 1) * 16);
    const uint32_t boff1 = (uint32_t)((nbase + rin + (lm >> 1) * 8) * STR1 + (lm & 1) * 16);
    const uint32_t boff2 = (uint32_t)((nbase + rin + (lm >> 1) * 8) * STR2 + (lm & 1) * 16);

    const int njmax = (nhalf == 1) ? 3 : 4;   // n 56-63 is all-pad

    const int chunk = blockIdx.y;
    for (int t = 0; t < 4; t++) {
        const int n0 = (chunk * 4 + t) * 128;

        // ---- stage desc tile -> A1 hi/lo panels ----
        {
            const float* dbase = desc + ((size_t)n0 * A_ + a) * D_IN;
            for (int idx = tid; idx < 128 * D_IN; idx += TPB) {
                int i = idx / D_IN, d = idx - i * D_IN;
                float x = dbase[(size_t)i * (A_ * D_IN) + d];
                uint32_t xb = __float_as_uint(x);
                uint32_t hb = xb & 0xFFFF0000u;                 // truncation split
                __nv_bfloat16 lo = __float2bfloat16(x - __uint_as_float(hb));
                uint32_t ad = sb + (uint32_t)(i * STR1 + d * 2);
                STS16(A1H + ad, (uint16_t)(xb >> 16));
                STS16(A1L + ad, __bfloat16_as_ushort(lo));
            }
        }
        __syncthreads();

        float acc[4][4];
#pragma unroll
        for (int nj = 0; nj < 4; nj++)
#pragma unroll
            for (int r = 0; r < 4; r++) acc[nj][r] = 0.0f;

        // ---- layer 1 MMAs: K = 48 (3 k16 steps), 3 split terms ----
#pragma unroll
        for (int ks = 0; ks < 3; ks++) {
            const uint32_t kb = ks * 32;
            uint32_t ah[4], al[4], bh[8], bl[8];
            ldsm4(ah, sb + A1H + aoff1 + kb);
            ldsm4(al, sb + A1L + aoff1 + kb);
            ldsm4(bh + 0, sb + B1H + boff1 + kb);
            ldsm4(bh + 4, sb + B1H + boff1 + 16 * STR1 + kb);
            ldsm4(bl + 0, sb + B1L + boff1 + kb);
            ldsm4(bl + 4, sb + B1L + boff1 + 16 * STR1 + kb);
#pragma unroll
            for (int nj = 0; nj < 4; nj++) {
                mma16816(acc[nj], ah, bh + 2 * nj);
                mma16816(acc[nj], al, bh + 2 * nj);
                mma16816(acc[nj], ah, bl + 2 * nj);
            }
        }

        // ---- epilogue 1: +b1, silu, split, write A2 hi/lo panels ----
        {
            float2 b1v[4];
#pragma unroll
            for (int nj = 0; nj < 4; nj++)
                b1v[nj] = *(const float2*)&sB1f[nbase + 8 * nj + 2 * tig];
#pragma unroll
            for (int nj = 0; nj < 4; nj++) {
                if (nj >= njmax) break;
                const float* c = acc[nj];
                float h0 = silu_f(c[0] + b1v[nj].x);
                float h1 = silu_f(c[1] + b1v[nj].y);
                float h2 = silu_f(c[2] + b1v[nj].x);
                float h3 = silu_f(c[3] + b1v[nj].y);
                uint32_t hb0 = __float_as_uint(h0) & 0xFFFF0000u;
                uint32_t hb1 = __float_as_uint(h1) & 0xFFFF0000u;
                uint32_t hb2 = __float_as_uint(h2) & 0xFFFF0000u;
                uint32_t hb3 = __float_as_uint(h3) & 0xFFFF0000u;
                uint32_t u01 = __byte_perm(hb0, hb1, 0x7632);
                uint32_t u23 = __byte_perm(hb2, hb3, 0x7632);
                uint32_t l01, l23;
                asm("cvt.rn.bf16x2.f32 %0, %1, %2;" : "=r"(l01)
                    : "f"(h1 - __uint_as_float(hb1)), "f"(h0 - __uint_as_float(hb0)));
                asm("cvt.rn.bf16x2.f32 %0, %1, %2;" : "=r"(l23)
                    : "f"(h3 - __uint_as_float(hb3)), "f"(h2 - __uint_as_float(hb2)));
                uint32_t r0 = (uint32_t)(mbase + g);
                uint32_t c0 = (uint32_t)(nbase + nj * 8 + 2 * tig);
                uint32_t ad = sb + r0 * STR2 + c0 * 2;
                STS32(A2H + ad, u01);
                STS32(A2H + ad + 8 * STR2, u23);
                STS32(A2L + ad, l01);
                STS32(A2L + ad + 8 * STR2, l23);
            }
        }
        __syncthreads();

#pragma unroll
        for (int nj = 0; nj < 4; nj++)
#pragma unroll
            for (int r = 0; r < 4; r++) acc[nj][r] = 0.0f;

        // ---- layer 2 MMAs: K = 64 (4 k16 steps), 3 split terms ----
#pragma unroll
        for (int ks = 0; ks < 4; ks++) {
            const uint32_t kb = ks * 32;
            uint32_t ah[4], al[4], bh[8], bl[8];
            ldsm4(ah, sb + A2H + aoff2 + kb);
            ldsm4(al, sb + A2L + aoff2 + kb);
            ldsm4(bh + 0, sb + B2H + boff2 + kb);
            ldsm4(bh + 4, sb + B2H + boff2 + 16 * STR2 + kb);
            ldsm4(bl + 0, sb + B2L + boff2 + kb);
            ldsm4(bl + 4, sb + B2L + boff2 + 16 * STR2 + kb);
#pragma unroll
            for (int nj = 0; nj < 4; nj++) {
                mma16816(acc[nj], ah, bh + 2 * nj);
                mma16816(acc[nj], al, bh + 2 * nj);
                mma16816(acc[nj], ah, bl + 2 * nj);
            }
        }

        // ---- epilogue 2: +b2, silu, dot w3, reduce, write out ----
        {
            float2 b2v[4], w3v[4];
#pragma unroll
            for (int nj = 0; nj < 4; nj++) {
                b2v[nj] = *(const float2*)&sB2f[nbase + 8 * nj + 2 * tig];
                w3v[nj] = *(const float2*)&sW3f[nbase + 8 * nj + 2 * tig];
            }
            float p0 = 0.f, p1 = 0.f;    // rows mbase+g, mbase+g+8
#pragma unroll
            for (int nj = 0; nj < 4; nj++) {
                if (nj >= njmax) break;
                const float* c = acc[nj];
                p0 += silu_f(c[0] + b2v[nj].x) * w3v[nj].x
                    + silu_f(c[1] + b2v[nj].y) * w3v[nj].y;
                p1 += silu_f(c[2] + b2v[nj].x) * w3v[nj].x
                    + silu_f(c[3] + b2v[nj].y) * w3v[nj].y;
            }
            p0 += __shfl_xor_sync(0xFFFFFFFFu, p0, 1);
            p0 += __shfl_xor_sync(0xFFFFFFFFu, p0, 2);
            p1 += __shfl_xor_sync(0xFFFFFFFFu, p1, 1);
            p1 += __shfl_xor_sync(0xFFFFFFFFu, p1, 2);
            if (tig == 0) {
                sPart[nhalf * 128 + mbase + g]     = p0;
                sPart[nhalf * 128 + mbase + g + 8] = p1;
            }
            __syncthreads();
            if (tid < 128) {
                float o = sPart[tid] + sPart[128 + tid] + *sB3f;
                out[(size_t)(n0 + tid) * A_ + a] = o;
            }
        }
        __syncthreads();
    }
}

extern "C" void kernel_launch(void* const* d_in, const int* in_sizes, int n_in,
                              void* d_out, int out_size) {
    const float* desc    = (const float*)d_in[0];
    const int*   numbers = (const int*)  d_in[1];
    const float* W1      = (const float*)d_in[2];
    const float* b1      = (const float*)d_in[3];
    const float* W2      = (const float*)d_in[4];
    const float* b2      = (const float*)d_in[5];
    const float* W3      = (const float*)d_in[6];
    const float* b3      = (const float*)d_in[7];
    float* out = (float*)d_out;

    const int N = in_sizes[0] / (A_ * D_IN);   // 4096
    prep_kernel<<<S_, 256>>>(W1, W2);
    cudaFuncSetAttribute(atomic_mlp_mma, cudaFuncAttributeMaxDynamicSharedMemorySize, SMEM_BYTES);
    dim3 grid(A_, (unsigned)(N / 512));        // (256, 8)
    atomic_mlp_mma<<<grid, TPB, SMEM_BYTES>>>(desc, numbers, b1, b2, W3, b3, out);
}